// round 7
// baseline (speedup 1.0000x reference)
#include <cuda_runtime.h>
#include <cuda_bf16.h>
#include <cstdint>

// Problem constants
#define DD    256
#define HW    4096
#define NTOK  65536          // 16 * 4096
#define KCB   2048
#define QSIZE 16777216       // 16 * 256 * 4096
// out layout (float32): [0..QSIZE) q, [QSIZE] loss, [QSIZE+1] codebook_loss,
// [QSIZE+2] commitment_loss, [QSIZE+3 .. +KCB) counts

#define EPS_SEL 1.5e-3f

// Scratch (device globals — no allocs allowed)
__device__ float         g_c2[KCB];
__device__ float         g_z2[NTOK];
__device__ __nv_bfloat16 g_zs[(size_t)NTOK * DD];   // z_hi token-major (32 MB)
__device__ float         g_zt[(size_t)NTOK * DD];   // z fp32 token-major (64 MB)
__device__ __nv_bfloat16 g_cs[(size_t)KCB * 512];   // [c_hi(256)|c_lo(256)] (2 MB)
__device__ int           g_idx[NTOK];

// smem layout of main kernel (dynamic)
#define SM_A    0            // 128 x 528B rows (264 bf16, padded) = 67584
#define SM_B0   67584        // 64 x 144B rows  = 9216
#define SM_B1   76800
#define SM_C2   86016        // 2048 floats = 8192
#define SM_MAIN 94208

// ---------------------------------------------------------------------------
__device__ __forceinline__ uint32_t smem_u32(const void* p) {
    uint32_t a;
    asm("{ .reg .u64 t; cvta.to.shared.u64 t, %1; cvt.u32.u64 %0, t; }"
        : "=r"(a) : "l"(p));
    return a;
}
__device__ __forceinline__ void ldsm4(uint32_t* r, uint32_t addr) {
    asm volatile("ldmatrix.sync.aligned.m8n8.x4.shared.b16 {%0,%1,%2,%3}, [%4];"
                 : "=r"(r[0]), "=r"(r[1]), "=r"(r[2]), "=r"(r[3]) : "r"(addr));
}
__device__ __forceinline__ void mma16816(float* c, const uint32_t* a,
                                         const uint32_t* b) {
    asm volatile(
        "mma.sync.aligned.m16n8k16.row.col.f32.bf16.bf16.f32 "
        "{%0,%1,%2,%3}, {%4,%5,%6,%7}, {%8,%9}, {%0,%1,%2,%3};"
        : "+f"(c[0]), "+f"(c[1]), "+f"(c[2]), "+f"(c[3])
        : "r"(a[0]), "r"(a[1]), "r"(a[2]), "r"(a[3]), "r"(b[0]), "r"(b[1]));
}
__device__ __forceinline__ void cp16(uint32_t dst, const void* src) {
    asm volatile("cp.async.ca.shared.global [%0], [%1], 16;"
                 :: "r"(dst), "l"(src) : "memory");
}
#define CP_COMMIT() asm volatile("cp.async.commit_group;" ::: "memory")
#define CP_WAIT1()  asm volatile("cp.async.wait_group 1;" ::: "memory")
#define CP_WAIT0()  asm volatile("cp.async.wait_group 0;" ::: "memory")

__device__ __forceinline__ void cp_chunk(uint32_t dstbase, int qq, int tid) {
    const int ct = qq >> 3, kc = qq & 7;
    #pragma unroll
    for (int it = 0; it < 2; it++) {
        int p = tid + it * 256;
        int r = p >> 3, c16 = p & 7;
        const __nv_bfloat16* src =
            g_cs + (size_t)(ct * 64 + r) * 512 + kc * 64 + c16 * 8;
        cp16(dstbase + r * 144 + c16 * 16, src);
    }
}

// exact fp32 rescore; rounding of dist matches rounds 1-4 formula
__device__ __noinline__ unsigned long long rescore(int n, int k,
                                                   const float* __restrict__ cb) {
    const float4* zp = (const float4*)(g_zt + (size_t)n * DD);
    const float4* cr = (const float4*)(cb + (size_t)k * DD);
    float s0 = 0.f, s1 = 0.f, s2 = 0.f, s3 = 0.f;
    #pragma unroll 8
    for (int i = 0; i < 64; i++) {
        float4 a = zp[i], b = cr[i];
        s0 = fmaf(a.x, b.x, s0); s1 = fmaf(a.y, b.y, s1);
        s2 = fmaf(a.z, b.z, s2); s3 = fmaf(a.w, b.w, s3);
    }
    float dot  = (s0 + s1) + (s2 + s3);
    float dist = fmaf(-2.0f, dot, g_z2[n] + g_c2[k]);
    return ((unsigned long long)__float_as_uint(dist) << 32) | (unsigned)k;
}

// ---------------------------------------------------------------------------
__global__ void init_out_kernel(float* out) {
    int i = threadIdx.x + blockIdx.x * blockDim.x;
    if (i < 3 + KCB) out[QSIZE + i] = 0.0f;
}

__global__ void c2_kernel(const float* __restrict__ cb) {
    int warp = (threadIdx.x >> 5) + blockIdx.x * (blockDim.x >> 5);
    int lane = threadIdx.x & 31;
    if (warp >= KCB) return;
    const float* row = cb + (size_t)warp * DD;
    float s = 0.f;
    #pragma unroll
    for (int d = lane; d < DD; d += 32) { float v = row[d]; s = fmaf(v, v, s); }
    #pragma unroll
    for (int off = 16; off; off >>= 1) s += __shfl_down_sync(0xffffffffu, s, off);
    if (lane == 0) g_c2[warp] = s;
}

__global__ void z2_kernel(const float* __restrict__ z) {
    int n = threadIdx.x + blockIdx.x * blockDim.x;
    if (n >= NTOK) return;
    int b = n >> 12, hw = n & 4095;
    const float* p = z + (size_t)b * (DD * HW) + hw;
    float s = 0.f;
    #pragma unroll 8
    for (int d = 0; d < DD; d++) { float v = p[(size_t)d * HW]; s = fmaf(v, v, s); }
    g_z2[n] = s;
}

// codebook split: c = c_hi + c_lo (bf16 each)
__global__ void split_cb_kernel(const float* __restrict__ cb) {
    int idx = threadIdx.x + blockIdx.x * blockDim.x;   // k*256 + d
    if (idx >= KCB * DD) return;
    int k = idx >> 8, d = idx & 255;
    float c = cb[idx];
    __nv_bfloat16 h = __float2bfloat16(c);
    float l = c - __bfloat162float(h);
    g_cs[(size_t)k * 512 + d]       = h;
    g_cs[(size_t)k * 512 + 256 + d] = __float2bfloat16(l);
}

// transpose z -> token-major fp32 (g_zt) + bf16 (g_zs)
__global__ __launch_bounds__(256)
void tz_kernel(const float* __restrict__ z) {
    __shared__ float t[64][65];
    const int bx = blockIdx.x;
    const int hw0 = (bx & 63) * 64;
    const int d0  = ((bx >> 6) & 3) * 64;
    const int b   = bx >> 8;
    const float* zb = z + (size_t)b * (DD * HW);
    const int tid = threadIdx.x;
    #pragma unroll
    for (int it = 0; it < 16; it++) {
        int p = tid + it * 256;
        int dd = p >> 6, r = p & 63;
        t[dd][r] = zb[(size_t)(d0 + dd) * HW + hw0 + r];
    }
    __syncthreads();
    #pragma unroll
    for (int it = 0; it < 16; it++) {
        int p = tid + it * 256;
        int r = p >> 6, dd = p & 63;
        float v = t[dd][r];
        size_t n = (size_t)b * 4096 + hw0 + r;
        g_zt[n * 256 + d0 + dd] = v;
        g_zs[n * 256 + d0 + dd] = __float2bfloat16(v);
    }
}

// ---------------------------------------------------------------------------
// Main HMMA kernel: 128 tokens/CTA x 2048 codes, K=512 bf16 split contraction
// via mma.sync m16n8k16, fused approx-scan + inline exact rescore -> g_idx.
// ---------------------------------------------------------------------------
__global__ __launch_bounds__(256, 2)
void vq_mma_kernel(const float* __restrict__ cb) {
    extern __shared__ char smem[];
    const uint32_t sb = smem_u32(smem);
    float* c2s = (float*)(smem + SM_C2);
    const int tid  = threadIdx.x;
    const int lane = tid & 31;
    const int warp = tid >> 5;
    const int n0 = blockIdx.x * 128;

    // stage A (z_hi, 128 tokens x 256) into padded rows of 528B
    #pragma unroll
    for (int it = 0; it < 16; it++) {
        int p = tid + it * 256;
        int r = p >> 5, c8 = p & 31;
        uint4 v = *(const uint4*)(g_zs + (size_t)(n0 + r) * 256 + c8 * 8);
        *(uint4*)(smem + SM_A + r * 528 + c8 * 16) = v;
    }
    // stage c2
    #pragma unroll
    for (int it = 0; it < 2; it++) {
        int p = tid + it * 256;
        *(uint4*)(c2s + p * 4) = *(const uint4*)(g_c2 + p * 4);
    }
    // prefetch B chunk 0
    cp_chunk(sb + SM_B0, 0, tid);
    CP_COMMIT();

    const int tok0 = warp * 16;
    const int g    = lane >> 2;
    const int tig  = lane & 3;
    const int n_r0 = n0 + tok0 + g;
    const int n_r1 = n_r0 + 8;
    const uint32_t aBase = sb + SM_A + (tok0 + (lane & 15)) * 528 + (lane >> 4) * 16;
    const uint32_t bLane = ((lane & 7) + ((lane >> 4) << 3)) * 144
                         + ((lane >> 3) & 1) * 16;

    float m0 = __int_as_float(0x7f800000);
    float m1 = __int_as_float(0x7f800000);
    unsigned long long key0 = ~0ULL, key1 = ~0ULL;

    int q = 0;
    for (int ct = 0; ct < 32; ct++) {
        float acc[8][4];
        #pragma unroll
        for (int j = 0; j < 8; j++)
            #pragma unroll
            for (int c = 0; c < 4; c++) acc[j][c] = 0.f;

        for (int kc = 0; kc < 8; kc++, q++) {
            const uint32_t bufB = sb + SM_B0 + (q & 1) * 9216;
            if (q < 255) {
                cp_chunk(sb + SM_B0 + ((q + 1) & 1) * 9216, q + 1, tid);
                CP_COMMIT();
                CP_WAIT1();
            } else {
                CP_WAIT0();
            }
            __syncthreads();

            #pragma unroll
            for (int ks = 0; ks < 4; ks++) {
                const int kcol = (kc * 64 + ks * 16) & 255;   // A duplicated over K
                uint32_t af[4];
                ldsm4(af, aBase + kcol * 2);
                #pragma unroll
                for (int j = 0; j < 8; j += 2) {
                    uint32_t bf[4];
                    ldsm4(bf, bufB + bLane + j * 1152 + ks * 32);
                    mma16816(acc[j],     af, bf);
                    mma16816(acc[j + 1], af, bf + 2);
                }
            }
            __syncthreads();   // all reads of this buffer done before next issue
        }

        // fused scan: approx score + inline exact rescore
        #pragma unroll
        for (int j = 0; j < 8; j++) {
            const int k0 = ct * 64 + j * 8 + 2 * tig;
            {
                float s = fmaf(-2.f, acc[j][0], c2s[k0]);
                if (s < m0) m0 = s;
                if (s <= m0 + EPS_SEL) {
                    unsigned long long kx = rescore(n_r0, k0, cb);
                    if (kx < key0) key0 = kx;
                }
            }
            {
                float s = fmaf(-2.f, acc[j][1], c2s[k0 + 1]);
                if (s < m0) m0 = s;
                if (s <= m0 + EPS_SEL) {
                    unsigned long long kx = rescore(n_r0, k0 + 1, cb);
                    if (kx < key0) key0 = kx;
                }
            }
            {
                float s = fmaf(-2.f, acc[j][2], c2s[k0]);
                if (s < m1) m1 = s;
                if (s <= m1 + EPS_SEL) {
                    unsigned long long kx = rescore(n_r1, k0, cb);
                    if (kx < key1) key1 = kx;
                }
            }
            {
                float s = fmaf(-2.f, acc[j][3], c2s[k0 + 1]);
                if (s < m1) m1 = s;
                if (s <= m1 + EPS_SEL) {
                    unsigned long long kx = rescore(n_r1, k0 + 1, cb);
                    if (kx < key1) key1 = kx;
                }
            }
        }
    }

    // merge the 4 lanes (tig 0..3) that share each token row
    unsigned long long t;
    t = __shfl_xor_sync(0xffffffffu, key0, 1); if (t < key0) key0 = t;
    t = __shfl_xor_sync(0xffffffffu, key0, 2); if (t < key0) key0 = t;
    t = __shfl_xor_sync(0xffffffffu, key1, 1); if (t < key1) key1 = t;
    t = __shfl_xor_sync(0xffffffffu, key1, 2); if (t < key1) key1 = t;
    if (tig == 0) {
        g_idx[n_r0] = (int)(key0 & 0xFFFFFFFFu);
        g_idx[n_r1] = (int)(key1 & 0xFFFFFFFFu);
    }
}

// ---------------------------------------------------------------------------
// Output epilogue: q (straight-through), counts, fused SSE
// ---------------------------------------------------------------------------
__global__ __launch_bounds__(256)
void vq_out_kernel(const float* __restrict__ z, const float* __restrict__ cb,
                   float* __restrict__ out) {
    __shared__ float lred[8];
    const int tid = threadIdx.x;
    const int n0 = blockIdx.x * 128;
    const int b = n0 >> 12, hw0 = n0 & 4095;

    if (tid < 128) atomicAdd(out + QSIZE + 3 + g_idx[n0 + tid], 1.0f);

    const int tok  = tid & 127;
    const int half = tid >> 7;
    const int kidx = g_idx[n0 + tok];
    const float* crow = cb + (size_t)kidx * DD;
    float* qbase = out + (size_t)b * (DD * HW) + hw0 + tok;
    const float* zb2 = z + (size_t)b * (DD * HW) + hw0 + tok;
    float lsum = 0.f;
    #pragma unroll 4
    for (int d = half * 128; d < half * 128 + 128; d++) {
        float c  = crow[d];
        float zz = zb2[(size_t)d * HW];
        float df = zz - c;
        lsum = fmaf(df, df, lsum);
        qbase[(size_t)d * HW] = zz + (c - zz);   // == reference ST rounding
    }
    #pragma unroll
    for (int off = 16; off; off >>= 1) lsum += __shfl_down_sync(0xffffffffu, lsum, off);
    if ((tid & 31) == 0) lred[tid >> 5] = lsum;
    __syncthreads();
    if (tid == 0) {
        float s = 0.f;
        #pragma unroll
        for (int w = 0; w < 8; w++) s += lred[w];
        atomicAdd(out + QSIZE + 1, s);
    }
}

__global__ void finalize_kernel(float* out) {
    float sse = out[QSIZE + 1];
    float mse = sse / (float)((size_t)NTOK * DD);
    out[QSIZE]     = fmaf(0.25f, mse, mse);
    out[QSIZE + 1] = mse;
    out[QSIZE + 2] = mse;
}

// ---------------------------------------------------------------------------
extern "C" void kernel_launch(void* const* d_in, const int* in_sizes, int n_in,
                              void* d_out, int out_size) {
    const float* z  = (const float*)d_in[0];     // (16, 256, 64, 64)
    const float* cb = (const float*)d_in[1];     // (2048, 256)
    float* out = (float*)d_out;

    cudaFuncSetAttribute(vq_mma_kernel,
                         cudaFuncAttributeMaxDynamicSharedMemorySize, SM_MAIN);

    init_out_kernel<<<9, 256>>>(out);
    c2_kernel<<<KCB / 8, 256>>>(cb);
    z2_kernel<<<NTOK / 256, 256>>>(z);
    split_cb_kernel<<<KCB * DD / 256, 256>>>(cb);
    tz_kernel<<<4096, 256>>>(z);
    vq_mma_kernel<<<NTOK / 128, 256, SM_MAIN>>>(cb);
    vq_out_kernel<<<NTOK / 128, 256>>>(z, cb, out);
    finalize_kernel<<<1, 1>>>(out);
}